// round 8
// baseline (speedup 1.0000x reference)
#include <cuda_runtime.h>
#include <cuda_bf16.h>
#include <math.h>

#define Bb 64
#define Ss 4096
#define Aa 128
#define FD 512
#define HD 512
#define NCHUNK 32          // s-chunks for context split (4096/128)
#define SCHUNK 128         // s-rows per chunk

// ---- scratch (static device globals; no runtime allocation) ----
__device__ float g_proj_hidden[Bb * Aa];                 // 32 KB
__device__ float g_scores[Bb * Ss];                      // 1 MB
__device__ float g_partial[NCHUNK * Bb * FD];            // 4 MB
__device__ int   g_count[Bb];                            // last-CTA counters (self-resetting)

__device__ __forceinline__ float tanh_approx(float x) {
    float y;
    asm("tanh.approx.f32 %0, %1;" : "=f"(y) : "f"(x));
    return y;
}

// ---------------------------------------------------------------
// K1: proj_hidden[b,a] = sum_h hidden_state[b,h] * W_hidden[a,h]
// ---------------------------------------------------------------
__global__ void k_proj_hidden(const float* __restrict__ hs,
                              const float* __restrict__ W) {
    int warp = (blockIdx.x * blockDim.x + threadIdx.x) >> 5;
    int lane = threadIdx.x & 31;
    if (warp >= Bb * Aa) return;
    int b = warp >> 7;
    int a = warp & (Aa - 1);

    const float4* wrow = (const float4*)(W + (size_t)a * HD);
    const float4* hrow = (const float4*)(hs + (size_t)b * HD);
    float acc = 0.f;
#pragma unroll
    for (int i = 0; i < HD / 128; i++) {
        float4 w4 = wrow[lane + i * 32];
        float4 h4 = hrow[lane + i * 32];
        acc += w4.x * h4.x + w4.y * h4.y + w4.z * h4.z + w4.w * h4.w;
    }
#pragma unroll
    for (int off = 16; off; off >>= 1)
        acc += __shfl_xor_sync(0xFFFFFFFFu, acc, off);
    if (lane == 0) g_proj_hidden[warp] = acc;
}

// ---------------------------------------------------------------
// K2: scores[b,s] = sum_a tanh(pi[b,s,a] + ph[b,a]) * w_score[a]
// warp per 4 s-rows; 4 batched __ldcs float4 loads (proven form).
// ---------------------------------------------------------------
__global__ void k_scores(const float* __restrict__ pi,
                         const float* __restrict__ wscore) {
    int warp = (blockIdx.x * blockDim.x + threadIdx.x) >> 5;
    int lane = threadIdx.x & 31;
    if (warp >= (Bb * Ss) / 4) return;
    int srow0 = warp * 4;
    int b  = srow0 >> 12;
    int s0 = srow0 & (Ss - 1);

    float4 ph = ((const float4*)(g_proj_hidden + b * Aa))[lane];
    float4 ws = ((const float4*)wscore)[lane];

    const float4* base = (const float4*)pi + ((size_t)b * Ss + s0) * (Aa / 4) + lane;

    // batch all 4 loads first (MLP)
    float4 p0 = __ldcs(base + 0 * 32);
    float4 p1 = __ldcs(base + 1 * 32);
    float4 p2 = __ldcs(base + 2 * 32);
    float4 p3 = __ldcs(base + 3 * 32);

    float acc[4];
    acc[0] = tanh_approx(p0.x + ph.x) * ws.x + tanh_approx(p0.y + ph.y) * ws.y
           + tanh_approx(p0.z + ph.z) * ws.z + tanh_approx(p0.w + ph.w) * ws.w;
    acc[1] = tanh_approx(p1.x + ph.x) * ws.x + tanh_approx(p1.y + ph.y) * ws.y
           + tanh_approx(p1.z + ph.z) * ws.z + tanh_approx(p1.w + ph.w) * ws.w;
    acc[2] = tanh_approx(p2.x + ph.x) * ws.x + tanh_approx(p2.y + ph.y) * ws.y
           + tanh_approx(p2.z + ph.z) * ws.z + tanh_approx(p2.w + ph.w) * ws.w;
    acc[3] = tanh_approx(p3.x + ph.x) * ws.x + tanh_approx(p3.y + ph.y) * ws.y
           + tanh_approx(p3.z + ph.z) * ws.z + tanh_approx(p3.w + ph.w) * ws.w;

#pragma unroll
    for (int j = 0; j < 4; j++) {
#pragma unroll
        for (int off = 16; off; off >>= 1)
            acc[j] += __shfl_xor_sync(0xFFFFFFFFu, acc[j], off);
    }
    if (lane == 0) {
        float* out = g_scores + b * Ss + s0;
        out[0] = acc[0]; out[1] = acc[1]; out[2] = acc[2]; out[3] = acc[3];
    }
}

// ---------------------------------------------------------------
// K3: softmax over S per batch. weights written straight into d_out.
// ---------------------------------------------------------------
__global__ void k_softmax(float* __restrict__ weights) {
    int b   = blockIdx.x;
    int tid = threadIdx.x;
    int lane = tid & 31, wid = tid >> 5;
    const float* sc = g_scores + b * Ss;

    float v[16];
    float m = -INFINITY;
#pragma unroll
    for (int i = 0; i < 16; i++) {
        v[i] = sc[tid + i * 256];
        m = fmaxf(m, v[i]);
    }
    __shared__ float red[8];
#pragma unroll
    for (int off = 16; off; off >>= 1)
        m = fmaxf(m, __shfl_xor_sync(0xFFFFFFFFu, m, off));
    if (lane == 0) red[wid] = m;
    __syncthreads();
    float bm = red[0];
#pragma unroll
    for (int i = 1; i < 8; i++) bm = fmaxf(bm, red[i]);
    __syncthreads();

    float tsum = 0.f;
#pragma unroll
    for (int i = 0; i < 16; i++) {
        v[i] = __expf(v[i] - bm);
        tsum += v[i];
    }
#pragma unroll
    for (int off = 16; off; off >>= 1)
        tsum += __shfl_xor_sync(0xFFFFFFFFu, tsum, off);
    if (lane == 0) red[wid] = tsum;
    __syncthreads();
    float total = 0.f;
#pragma unroll
    for (int i = 0; i < 8; i++) total += red[i];
    float inv = 1.0f / total;

    float* wout = weights + b * Ss;
#pragma unroll
    for (int i = 0; i < 16; i++)
        wout[tid + i * 256] = v[i] * inv;
}

// ---------------------------------------------------------------
// K4: context partials + last-CTA final reduce (threadfence pattern).
// block = (chunk, b); 128 threads; streams SCHUNK s-rows with
// explicit 8-row load batches (MLP=8). The last block to finish
// for each b reduces all NCHUNK partials in fixed chunk order
// (bit-deterministic) and resets the counter for graph replay.
// grid: dim3(NCHUNK, Bb) x 128 = 2048 CTAs
// ---------------------------------------------------------------
__global__ void k_context(const float* __restrict__ feat,
                          const float* __restrict__ weights,
                          float* __restrict__ ctx) {
    int chunk = blockIdx.x;
    int b     = blockIdx.y;
    int tid   = threadIdx.x;           // owns d = tid*4..tid*4+3
    int s0    = chunk * SCHUNK;

    __shared__ float wsh[SCHUNK];
    if (tid < SCHUNK) wsh[tid] = weights[b * Ss + s0 + tid];
    __syncthreads();

    const float4* f = (const float4*)feat + ((size_t)b * Ss + s0) * (FD / 4) + tid;
    float4 acc = make_float4(0.f, 0.f, 0.f, 0.f);

    for (int s = 0; s < SCHUNK; s += 8) {
        float4 xr[8];
#pragma unroll
        for (int j = 0; j < 8; j++)
            xr[j] = __ldcs(f + (size_t)(s + j) * (FD / 4));
#pragma unroll
        for (int j = 0; j < 8; j++) {
            float w = wsh[s + j];
            acc.x += w * xr[j].x; acc.y += w * xr[j].y;
            acc.z += w * xr[j].z; acc.w += w * xr[j].w;
        }
    }
    float4* out = (float4*)(g_partial + ((size_t)chunk * Bb + b) * FD) + tid;
    *out = acc;

    // ---- last-CTA reduction for this b ----
    __threadfence();
    __shared__ int isLast;
    if (tid == 0) {
        int old = atomicAdd(&g_count[b], 1);
        isLast = (old == NCHUNK - 1);
    }
    __syncthreads();
    if (isLast) {
        __threadfence();
        float4 r = make_float4(0.f, 0.f, 0.f, 0.f);
#pragma unroll
        for (int c = 0; c < NCHUNK; c++) {
            const float4* p = (const float4*)(g_partial + ((size_t)c * Bb + b) * FD) + tid;
            float4 v = __ldcg(p);
            r.x += v.x; r.y += v.y; r.z += v.z; r.w += v.w;
        }
        ((float4*)(ctx + (size_t)b * FD))[tid] = r;
        if (tid == 0) g_count[b] = 0;   // reset for next graph replay
    }
}

// ---------------------------------------------------------------
extern "C" void kernel_launch(void* const* d_in, const int* in_sizes, int n_in,
                              void* d_out, int out_size) {
    const float* proj_image     = (const float*)d_in[0];  // [B,S,A]
    const float* image_features = (const float*)d_in[1];  // [B,S,FDIM]
    const float* hidden_state   = (const float*)d_in[2];  // [B,HDIM]
    const float* W_hidden       = (const float*)d_in[3];  // [A,HDIM]
    const float* w_score        = (const float*)d_in[4];  // [A]

    float* out     = (float*)d_out;
    float* ctx     = out;              // [B, FDIM]
    float* weights = out + Bb * FD;    // [B, S]

    k_proj_hidden<<<(Bb * Aa * 32) / 256, 256>>>(hidden_state, W_hidden);
    k_scores<<<(Bb * Ss / 4) * 32 / 256, 256>>>(proj_image, w_score);
    k_softmax<<<Bb, 256>>>(weights);
    k_context<<<dim3(NCHUNK, Bb), 128>>>(image_features, weights, ctx);
}

// round 9
// speedup vs baseline: 1.0351x; 1.0351x over previous
#include <cuda_runtime.h>
#include <cuda_bf16.h>
#include <math.h>

#define Bb 64
#define Ss 4096
#define Aa 128
#define FD 512
#define HD 512
#define NCHUNK 32          // s-chunks for context split (4096/128)
#define SCHUNK 128         // s-rows per chunk

// ---- scratch (static device globals; no runtime allocation) ----
__device__ float g_proj_hidden[Bb * Aa];                 // 32 KB
__device__ float g_scores[Bb * Ss];                      // 1 MB
__device__ float g_partial[NCHUNK * Bb * FD];            // 4 MB

__device__ __forceinline__ float tanh_approx(float x) {
    float y;
    asm("tanh.approx.f32 %0, %1;" : "=f"(y) : "f"(x));
    return y;
}

// ---------------------------------------------------------------
// K1: proj_hidden[b,a] = sum_h hidden_state[b,h] * W_hidden[a,h]
// ---------------------------------------------------------------
__global__ void k_proj_hidden(const float* __restrict__ hs,
                              const float* __restrict__ W) {
    int warp = (blockIdx.x * blockDim.x + threadIdx.x) >> 5;
    int lane = threadIdx.x & 31;
    if (warp >= Bb * Aa) return;
    int b = warp >> 7;
    int a = warp & (Aa - 1);

    const float4* wrow = (const float4*)(W + (size_t)a * HD);
    const float4* hrow = (const float4*)(hs + (size_t)b * HD);
    float acc = 0.f;
#pragma unroll
    for (int i = 0; i < HD / 128; i++) {
        float4 w4 = wrow[lane + i * 32];
        float4 h4 = hrow[lane + i * 32];
        acc += w4.x * h4.x + w4.y * h4.y + w4.z * h4.z + w4.w * h4.w;
    }
#pragma unroll
    for (int off = 16; off; off >>= 1)
        acc += __shfl_xor_sync(0xFFFFFFFFu, acc, off);
    if (lane == 0) g_proj_hidden[warp] = acc;
}

// ---------------------------------------------------------------
// K2: scores[b,s] = sum_a tanh(pi[b,s,a] + ph[b,a]) * w_score[a]
// warp per 4 s-rows; 4 batched __ldcs float4 loads (proven form).
// grid: Bb*Ss/4 warps = 65536 warps -> 8192 blocks x 256
// ---------------------------------------------------------------
__global__ void k_scores(const float* __restrict__ pi,
                         const float* __restrict__ wscore) {
    int warp = (blockIdx.x * blockDim.x + threadIdx.x) >> 5;
    int lane = threadIdx.x & 31;
    if (warp >= (Bb * Ss) / 4) return;
    int srow0 = warp * 4;
    int b  = srow0 >> 12;
    int s0 = srow0 & (Ss - 1);

    float4 ph = ((const float4*)(g_proj_hidden + b * Aa))[lane];
    float4 ws = ((const float4*)wscore)[lane];

    const float4* base = (const float4*)pi + ((size_t)b * Ss + s0) * (Aa / 4) + lane;

    // batch all 4 loads first (MLP)
    float4 p0 = __ldcs(base + 0 * 32);
    float4 p1 = __ldcs(base + 1 * 32);
    float4 p2 = __ldcs(base + 2 * 32);
    float4 p3 = __ldcs(base + 3 * 32);

    float acc[4];
    acc[0] = tanh_approx(p0.x + ph.x) * ws.x + tanh_approx(p0.y + ph.y) * ws.y
           + tanh_approx(p0.z + ph.z) * ws.z + tanh_approx(p0.w + ph.w) * ws.w;
    acc[1] = tanh_approx(p1.x + ph.x) * ws.x + tanh_approx(p1.y + ph.y) * ws.y
           + tanh_approx(p1.z + ph.z) * ws.z + tanh_approx(p1.w + ph.w) * ws.w;
    acc[2] = tanh_approx(p2.x + ph.x) * ws.x + tanh_approx(p2.y + ph.y) * ws.y
           + tanh_approx(p2.z + ph.z) * ws.z + tanh_approx(p2.w + ph.w) * ws.w;
    acc[3] = tanh_approx(p3.x + ph.x) * ws.x + tanh_approx(p3.y + ph.y) * ws.y
           + tanh_approx(p3.z + ph.z) * ws.z + tanh_approx(p3.w + ph.w) * ws.w;

#pragma unroll
    for (int j = 0; j < 4; j++) {
#pragma unroll
        for (int off = 16; off; off >>= 1)
            acc[j] += __shfl_xor_sync(0xFFFFFFFFu, acc[j], off);
    }
    if (lane == 0) {
        float* out = g_scores + b * Ss + s0;
        out[0] = acc[0]; out[1] = acc[1]; out[2] = acc[2]; out[3] = acc[3];
    }
}

// ---------------------------------------------------------------
// K3: softmax over S per batch. 512 threads, 8 elems/thread.
// weights written straight into d_out.
// ---------------------------------------------------------------
__global__ void k_softmax(float* __restrict__ weights) {
    int b   = blockIdx.x;
    int tid = threadIdx.x;             // 0..511
    int lane = tid & 31, wid = tid >> 5;   // 16 warps
    const float* sc = g_scores + b * Ss;

    float v[8];
    float m = -INFINITY;
#pragma unroll
    for (int i = 0; i < 8; i++) {
        v[i] = sc[tid + i * 512];
        m = fmaxf(m, v[i]);
    }
    __shared__ float red[16];
#pragma unroll
    for (int off = 16; off; off >>= 1)
        m = fmaxf(m, __shfl_xor_sync(0xFFFFFFFFu, m, off));
    if (lane == 0) red[wid] = m;
    __syncthreads();
    float bm = red[0];
#pragma unroll
    for (int i = 1; i < 16; i++) bm = fmaxf(bm, red[i]);
    __syncthreads();

    float tsum = 0.f;
#pragma unroll
    for (int i = 0; i < 8; i++) {
        v[i] = __expf(v[i] - bm);
        tsum += v[i];
    }
#pragma unroll
    for (int off = 16; off; off >>= 1)
        tsum += __shfl_xor_sync(0xFFFFFFFFu, tsum, off);
    if (lane == 0) red[wid] = tsum;
    __syncthreads();
    float total = 0.f;
#pragma unroll
    for (int i = 0; i < 16; i++) total += red[i];
    float inv = 1.0f / total;

    float* wout = weights + b * Ss;
#pragma unroll
    for (int i = 0; i < 8; i++)
        wout[tid + i * 512] = v[i] * inv;
}

// ---------------------------------------------------------------
// K4: context partials. block = (chunk, b); 128 threads; streams
// SCHUNK s-rows. Explicit 8-row load batches (MLP=8). Pure
// streaming — no fences, no atomics (measured fastest form).
// grid: dim3(NCHUNK, Bb) x 128 = 2048 CTAs
// ---------------------------------------------------------------
__global__ void k_context(const float* __restrict__ feat,
                          const float* __restrict__ weights) {
    int chunk = blockIdx.x;
    int b     = blockIdx.y;
    int tid   = threadIdx.x;           // owns d = tid*4..tid*4+3
    int s0    = chunk * SCHUNK;

    __shared__ float wsh[SCHUNK];
    if (tid < SCHUNK) wsh[tid] = weights[b * Ss + s0 + tid];
    __syncthreads();

    const float4* f = (const float4*)feat + ((size_t)b * Ss + s0) * (FD / 4) + tid;
    float4 acc = make_float4(0.f, 0.f, 0.f, 0.f);

    for (int s = 0; s < SCHUNK; s += 8) {
        float4 xr[8];
#pragma unroll
        for (int j = 0; j < 8; j++)
            xr[j] = __ldcs(f + (size_t)(s + j) * (FD / 4));
#pragma unroll
        for (int j = 0; j < 8; j++) {
            float w = wsh[s + j];
            acc.x += w * xr[j].x; acc.y += w * xr[j].y;
            acc.z += w * xr[j].z; acc.w += w * xr[j].w;
        }
    }
    float4* out = (float4*)(g_partial + ((size_t)chunk * Bb + b) * FD) + tid;
    *out = acc;
}

// ---------------------------------------------------------------
// K5: reduce NCHUNK chunk-partials -> context (deterministic order).
// ---------------------------------------------------------------
__global__ void k_reduce(float* __restrict__ ctx) {
    int i = blockIdx.x * blockDim.x + threadIdx.x;   // [0, Bb*FD)
    float acc = 0.f;
#pragma unroll
    for (int c = 0; c < NCHUNK; c++)
        acc += g_partial[(size_t)c * Bb * FD + i];
    ctx[i] = acc;
}

// ---------------------------------------------------------------
extern "C" void kernel_launch(void* const* d_in, const int* in_sizes, int n_in,
                              void* d_out, int out_size) {
    const float* proj_image     = (const float*)d_in[0];  // [B,S,A]
    const float* image_features = (const float*)d_in[1];  // [B,S,FDIM]
    const float* hidden_state   = (const float*)d_in[2];  // [B,HDIM]
    const float* W_hidden       = (const float*)d_in[3];  // [A,HDIM]
    const float* w_score        = (const float*)d_in[4];  // [A]

    float* out     = (float*)d_out;
    float* ctx     = out;              // [B, FDIM]
    float* weights = out + Bb * FD;    // [B, S]

    k_proj_hidden<<<(Bb * Aa * 32) / 256, 256>>>(hidden_state, W_hidden);
    k_scores<<<(Bb * Ss / 4) * 32 / 256, 256>>>(proj_image, w_score);
    k_softmax<<<Bb, 512>>>(weights);
    k_context<<<dim3(NCHUNK, Bb), 128>>>(image_features, weights);
    k_reduce<<<Bb, 512>>>(ctx);
}

// round 16
// speedup vs baseline: 1.0354x; 1.0003x over previous
#include <cuda_runtime.h>
#include <cuda_bf16.h>
#include <math.h>

#define Bb 64
#define Ss 4096
#define Aa 128
#define FD 512
#define HD 512
#define NCHUNK 32          // s-chunks for context split (4096/128)
#define SCHUNK 128         // s-rows per chunk

// ---- scratch (static device globals; no runtime allocation) ----
__device__ float g_proj_hidden[Bb * Aa];                 // 32 KB
__device__ float g_scores[Bb * Ss];                      // 1 MB
__device__ float g_partial[NCHUNK * Bb * FD];            // 4 MB

__device__ __forceinline__ float tanh_approx(float x) {
    float y;
    asm("tanh.approx.f32 %0, %1;" : "=f"(y) : "f"(x));
    return y;
}

// ---------------------------------------------------------------
// K1: proj_hidden[b,a] = sum_h hidden_state[b,h] * W_hidden[a,h]
// No explicit PDL trigger: implicit trigger at grid completion
// guarantees g_proj_hidden is visible to k_scores' grid-dep sync.
// ---------------------------------------------------------------
__global__ void k_proj_hidden(const float* __restrict__ hs,
                              const float* __restrict__ W) {
    int warp = (blockIdx.x * blockDim.x + threadIdx.x) >> 5;
    int lane = threadIdx.x & 31;
    if (warp >= Bb * Aa) return;
    int b = warp >> 7;
    int a = warp & (Aa - 1);

    const float4* wrow = (const float4*)(W + (size_t)a * HD);
    const float4* hrow = (const float4*)(hs + (size_t)b * HD);
    float acc = 0.f;
#pragma unroll
    for (int i = 0; i < HD / 128; i++) {
        float4 w4 = wrow[lane + i * 32];
        float4 h4 = hrow[lane + i * 32];
        acc += w4.x * h4.x + w4.y * h4.y + w4.z * h4.z + w4.w * h4.w;
    }
#pragma unroll
    for (int off = 16; off; off >>= 1)
        acc += __shfl_xor_sync(0xFFFFFFFFu, acc, off);
    if (lane == 0) g_proj_hidden[warp] = acc;
}

// ---------------------------------------------------------------
// K2: scores[b,s] = sum_a tanh(pi[b,s,a] + ph[b,a]) * w_score[a]
// PDL: launches while K1 runs; independent prefix (proj_image
// streaming loads) overlaps K1; grid-dep sync before reading
// g_proj_hidden.
// ---------------------------------------------------------------
__global__ void k_scores(const float* __restrict__ pi,
                         const float* __restrict__ wscore) {
    int warp = (blockIdx.x * blockDim.x + threadIdx.x) >> 5;
    int lane = threadIdx.x & 31;
    if (warp >= (Bb * Ss) / 4) return;
    int srow0 = warp * 4;
    int b  = srow0 >> 12;
    int s0 = srow0 & (Ss - 1);

    const float4* base = (const float4*)pi + ((size_t)b * Ss + s0) * (Aa / 4) + lane;

    // independent prefix: batch all 4 streaming loads (MLP=4)
    float4 p0 = __ldcs(base + 0 * 32);
    float4 p1 = __ldcs(base + 1 * 32);
    float4 p2 = __ldcs(base + 2 * 32);
    float4 p3 = __ldcs(base + 3 * 32);
    float4 ws = ((const float4*)wscore)[lane];

    cudaGridDependencySynchronize();          // wait for k_proj_hidden completion
    float4 ph = ((const float4*)(g_proj_hidden + b * Aa))[lane];

    float acc[4];
    acc[0] = tanh_approx(p0.x + ph.x) * ws.x + tanh_approx(p0.y + ph.y) * ws.y
           + tanh_approx(p0.z + ph.z) * ws.z + tanh_approx(p0.w + ph.w) * ws.w;
    acc[1] = tanh_approx(p1.x + ph.x) * ws.x + tanh_approx(p1.y + ph.y) * ws.y
           + tanh_approx(p1.z + ph.z) * ws.z + tanh_approx(p1.w + ph.w) * ws.w;
    acc[2] = tanh_approx(p2.x + ph.x) * ws.x + tanh_approx(p2.y + ph.y) * ws.y
           + tanh_approx(p2.z + ph.z) * ws.z + tanh_approx(p2.w + ph.w) * ws.w;
    acc[3] = tanh_approx(p3.x + ph.x) * ws.x + tanh_approx(p3.y + ph.y) * ws.y
           + tanh_approx(p3.z + ph.z) * ws.z + tanh_approx(p3.w + ph.w) * ws.w;

#pragma unroll
    for (int j = 0; j < 4; j++) {
#pragma unroll
        for (int off = 16; off; off >>= 1)
            acc[j] += __shfl_xor_sync(0xFFFFFFFFu, acc[j], off);
    }
    if (lane == 0) {
        float* out = g_scores + b * Ss + s0;
        out[0] = acc[0]; out[1] = acc[1]; out[2] = acc[2]; out[3] = acc[3];
    }
}

// ---------------------------------------------------------------
// K3: softmax over S per batch. 512 threads, 8 elems/thread.
// Grid-dep sync before reading g_scores.
// ---------------------------------------------------------------
__global__ void k_softmax(float* __restrict__ weights) {
    int b   = blockIdx.x;
    int tid = threadIdx.x;             // 0..511
    int lane = tid & 31, wid = tid >> 5;   // 16 warps
    const float* sc = g_scores + b * Ss;

    cudaGridDependencySynchronize();          // wait for k_scores completion

    float v[8];
    float m = -INFINITY;
#pragma unroll
    for (int i = 0; i < 8; i++) {
        v[i] = sc[tid + i * 512];
        m = fmaxf(m, v[i]);
    }
    __shared__ float red[16];
#pragma unroll
    for (int off = 16; off; off >>= 1)
        m = fmaxf(m, __shfl_xor_sync(0xFFFFFFFFu, m, off));
    if (lane == 0) red[wid] = m;
    __syncthreads();
    float bm = red[0];
#pragma unroll
    for (int i = 1; i < 16; i++) bm = fmaxf(bm, red[i]);
    __syncthreads();

    float tsum = 0.f;
#pragma unroll
    for (int i = 0; i < 8; i++) {
        v[i] = __expf(v[i] - bm);
        tsum += v[i];
    }
#pragma unroll
    for (int off = 16; off; off >>= 1)
        tsum += __shfl_xor_sync(0xFFFFFFFFu, tsum, off);
    if (lane == 0) red[wid] = tsum;
    __syncthreads();
    float total = 0.f;
#pragma unroll
    for (int i = 0; i < 16; i++) total += red[i];
    float inv = 1.0f / total;

    float* wout = weights + b * Ss;
#pragma unroll
    for (int i = 0; i < 8; i++)
        wout[tid + i * 512] = v[i] * inv;
}

// ---------------------------------------------------------------
// K4: context partials. block = (chunk, b); 128 threads; streams
// SCHUNK s-rows, 8-row load batches (MLP=8). PDL: first feat batch
// (independent of weights) prefetched before the grid-dep sync.
// grid: dim3(NCHUNK, Bb) x 128 = 2048 CTAs
// ---------------------------------------------------------------
__global__ void k_context(const float* __restrict__ feat,
                          const float* __restrict__ weights) {
    int chunk = blockIdx.x;
    int b     = blockIdx.y;
    int tid   = threadIdx.x;           // owns d = tid*4..tid*4+3
    int s0    = chunk * SCHUNK;

    const float4* f = (const float4*)feat + ((size_t)b * Ss + s0) * (FD / 4) + tid;

    // independent prefix: prefetch first 8-row batch while softmax runs
    float4 xr0[8];
#pragma unroll
    for (int j = 0; j < 8; j++)
        xr0[j] = __ldcs(f + (size_t)j * (FD / 4));

    cudaGridDependencySynchronize();          // wait for k_softmax completion

    __shared__ float wsh[SCHUNK];
    if (tid < SCHUNK) wsh[tid] = weights[b * Ss + s0 + tid];
    __syncthreads();

    float4 acc = make_float4(0.f, 0.f, 0.f, 0.f);
#pragma unroll
    for (int j = 0; j < 8; j++) {
        float w = wsh[j];
        acc.x += w * xr0[j].x; acc.y += w * xr0[j].y;
        acc.z += w * xr0[j].z; acc.w += w * xr0[j].w;
    }

    for (int s = 8; s < SCHUNK; s += 8) {
        float4 xr[8];
#pragma unroll
        for (int j = 0; j < 8; j++)
            xr[j] = __ldcs(f + (size_t)(s + j) * (FD / 4));
#pragma unroll
        for (int j = 0; j < 8; j++) {
            float w = wsh[s + j];
            acc.x += w * xr[j].x; acc.y += w * xr[j].y;
            acc.z += w * xr[j].z; acc.w += w * xr[j].w;
        }
    }
    float4* out = (float4*)(g_partial + ((size_t)chunk * Bb + b) * FD) + tid;
    *out = acc;
}

// ---------------------------------------------------------------
// K5: reduce NCHUNK chunk-partials -> context (deterministic order).
// ---------------------------------------------------------------
__global__ void k_reduce(float* __restrict__ ctx) {
    cudaGridDependencySynchronize();          // wait for k_context completion
    int i = blockIdx.x * blockDim.x + threadIdx.x;   // [0, Bb*FD)
    float acc = 0.f;
#pragma unroll
    for (int c = 0; c < NCHUNK; c++)
        acc += g_partial[(size_t)c * Bb * FD + i];
    ctx[i] = acc;
}

// ---------------------------------------------------------------
// Non-template PDL launcher (void*-based, no template deduction).
static void launch_pdl(const void* fn, dim3 grid, dim3 block, void** args) {
    cudaLaunchConfig_t cfg = {};
    cfg.gridDim  = grid;
    cfg.blockDim = block;
    cfg.stream   = 0;   // legacy default stream (same as <<<>>>)
    cudaLaunchAttribute attr[1];
    attr[0].id = cudaLaunchAttributeProgrammaticStreamSerialization;
    attr[0].val.programmaticStreamSerializationAllowed = 1;
    cfg.attrs = attr;
    cfg.numAttrs = 1;
    cudaLaunchKernelExC(&cfg, fn, args);
}

extern "C" void kernel_launch(void* const* d_in, const int* in_sizes, int n_in,
                              void* d_out, int out_size) {
    const float* proj_image     = (const float*)d_in[0];  // [B,S,A]
    const float* image_features = (const float*)d_in[1];  // [B,S,FDIM]
    const float* hidden_state   = (const float*)d_in[2];  // [B,HDIM]
    const float* W_hidden       = (const float*)d_in[3];  // [A,HDIM]
    const float* w_score        = (const float*)d_in[4];  // [A]

    float* out     = (float*)d_out;
    float* ctx     = out;              // [B, FDIM]
    float* weights = out + Bb * FD;    // [B, S]

    k_proj_hidden<<<(Bb * Aa * 32) / 256, 256>>>(hidden_state, W_hidden);

    {
        void* args[] = { (void*)&proj_image, (void*)&w_score };
        launch_pdl((const void*)k_scores,
                   dim3((Bb * Ss / 4) * 32 / 256), dim3(256), args);
    }
    {
        void* args[] = { (void*)&weights };
        launch_pdl((const void*)k_softmax, dim3(Bb), dim3(512), args);
    }
    {
        void* args[] = { (void*)&image_features, (void*)&weights };
        launch_pdl((const void*)k_context, dim3(NCHUNK, Bb), dim3(128), args);
    }
    {
        void* args[] = { (void*)&ctx };
        launch_pdl((const void*)k_reduce, dim3(Bb), dim3(512), args);
    }
}